// round 13
// baseline (speedup 1.0000x reference)
#include <cuda_runtime.h>
#include <cstdint>

#define T_LEN 131072
#define D_X 16
#define D_L 8

// d_out layout (flat concat of reference tuple, all float32)
#define OFF_RECON 0
#define OFF_PRED  (T_LEN * D_X)
#define OFF_LMP   (2 * T_LEN * D_X)
#define OFF_LVP   (OFF_LMP + 2 * T_LEN * D_L)
#define OFF_CT    (OFF_LVP + 2 * T_LEN * D_L)
#define OFF_CT1   (OFF_CT + T_LEN * D_X * D_L)

typedef unsigned long long u64;

// ---------------------------------------------------------------------------
// Packed fp32x2 helpers (verified head path)
// ---------------------------------------------------------------------------
__device__ __forceinline__ u64 pk2(float x, float y) {
    u64 r;
    asm("mov.b64 %0, {%1, %2};" : "=l"(r) : "f"(x), "f"(y));
    return r;
}
__device__ __forceinline__ void upk2(u64 a, float& x, float& y) {
    asm("mov.b64 {%0, %1}, %2;" : "=f"(x), "=f"(y) : "l"(a));
}
__device__ __forceinline__ u64 ffma2u(u64 a, u64 b, u64 c) {
    u64 d;
    asm("fma.rn.f32x2 %0, %1, %2, %3;" : "=l"(d) : "l"(a), "l"(b), "l"(c));
    return d;
}

// tf32 conversion + mma
__device__ __forceinline__ float cvt_tf32(float x) {
    float r;
    asm("cvt.rna.tf32.f32 %0, %1;" : "=f"(r) : "f"(x));
    return r;
}
__device__ __forceinline__ void mma_tf32(float* c, const unsigned* a,
                                         const unsigned* b) {
    asm volatile(
        "mma.sync.aligned.m16n8k8.row.col.f32.tf32.tf32.f32 "
        "{%0,%1,%2,%3}, {%4,%5,%6,%7}, {%8,%9}, {%0,%1,%2,%3};"
        : "+f"(c[0]), "+f"(c[1]), "+f"(c[2]), "+f"(c[3])
        : "r"(a[0]), "r"(a[1]), "r"(a[2]), "r"(a[3]), "r"(b[0]), "r"(b[1]));
}

// ---------------------------------------------------------------------------
// Device-global scratch (no allocation).
// g_wf: fragment-major W per node: [n][nh][nt][c][lane] -> float4 over kt,
//       value = tf32(W[j = nh*32+nt*8+(lane>>2)][k = kt*8 + c*4 + (lane&3)])
// ---------------------------------------------------------------------------
__device__ __align__(16) float g_wf[D_X * 2048];
__device__ __align__(16) float g_w12[D_X * 64];       // collapsed lw1@lw2
__device__ __align__(16) float g_beff[D_X];           // lb1@lw2 + lb2

// grid = 16 (one CTA per node), block = 256
__global__ void prep_kernel(const float* __restrict__ lw0,
                            const float* __restrict__ lw1,
                            const float* __restrict__ lw2,
                            const float* __restrict__ lb0,
                            const float* __restrict__ lb1,
                            const float* __restrict__ lb2,
                            float* __restrict__ out) {
    int n = blockIdx.x;
    int tid = threadIdx.x;
#pragma unroll
    for (int s = 0; s < 2; s++) {
        int idx = tid + s * 256;         // 0..511 float4 slots
        int l  = idx & 31;
        int c  = (idx >> 5) & 1;
        int nt = (idx >> 6) & 3;
        int nh = idx >> 8;
        int j = nh * 32 + nt * 8 + (l >> 2);
        int kb = c * 4 + (l & 3);
        float4 v;
        v.x = cvt_tf32(lw0[(n * 32 + (kb))      * 64 + j]);
        v.y = cvt_tf32(lw0[(n * 32 + (8 + kb))  * 64 + j]);
        v.z = cvt_tf32(lw0[(n * 32 + (16 + kb)) * 64 + j]);
        v.w = cvt_tf32(lw0[(n * 32 + (24 + kb)) * 64 + j]);
        ((float4*)(g_wf + n * 2048))[idx] = v;
    }
    if (tid < 64) {
        int j = tid;
        float acc = 0.f;
#pragma unroll 8
        for (int o = 0; o < 64; o++)
            acc = fmaf(lw1[(n * 64 + j) * 64 + o], lw2[n * 64 + o], acc);
        g_w12[n * 64 + j] = acc;
        if (j == 0) {
            float b = lb2[n];
            for (int o = 0; o < 64; o++)
                b = fmaf(lb1[n * 64 + o], lw2[n * 64 + o], b);
            g_beff[n] = b;
        }
    }
    __syncthreads();
    if (tid == 0) {
        float s = g_beff[n];
        for (int o = 0; o < 64; o++) {
            float h = fmaxf(lb0[n * 64 + o], 0.f);
            s = fmaf(h, g_w12[n * 64 + o], s);
        }
        out[OFF_PRED + n] = fmaxf(s, 0.f);
    }
}

// ---------------------------------------------------------------------------
// Encoder (verified round-2 arithmetic): packed smem block per branch.
// ---------------------------------------------------------------------------
#define EW0 0
#define EB0 8
#define EW1 16
#define EB1 80
#define EW2 88
#define EB2 1112
#define ESZ 1240

__device__ __forceinline__ void enc01h(float s, const float* __restrict__ w,
                                       float* __restrict__ h1) {
    float h0[8];
#pragma unroll
    for (int i = 0; i < 8; i++) {
        float v = fmaf(s, w[EW0 + i], w[EB0 + i]);
        h0[i] = v > 0.f ? v : 0.01f * v;
    }
#pragma unroll
    for (int j = 0; j < 8; j++) {
        float a = 0.f;
#pragma unroll
        for (int i = 0; i < 8; i++) a = fmaf(h0[i], w[EW1 + i * 8 + j], a);
        a += w[EB1 + j];
        h1[j] = a > 0.f ? a : 0.01f * a;
    }
}

__device__ __forceinline__ void enc_branch_cont(float s, const float* __restrict__ w,
                                                float* __restrict__ dst) {
    float h1[8];
    enc01h(s, w, h1);
#pragma unroll 4
    for (int m = 0; m < 128; m += 4) {
        float4 a = make_float4(0.f, 0.f, 0.f, 0.f);
#pragma unroll
        for (int j = 0; j < 8; j++) {
            float4 ww = *(const float4*)&w[EW2 + j * 128 + m];
            a.x = fmaf(h1[j], ww.x, a.x);
            a.y = fmaf(h1[j], ww.y, a.y);
            a.z = fmaf(h1[j], ww.z, a.z);
            a.w = fmaf(h1[j], ww.w, a.w);
        }
        a.x += w[EB2 + m + 0];
        a.y += w[EB2 + m + 1];
        a.z += w[EB2 + m + 2];
        a.w += w[EB2 + m + 3];
        *(float4*)&dst[m] = a;
    }
}

__device__ __forceinline__ void enc_branch_bin(float s, const float* __restrict__ w,
                                               float* __restrict__ dst,
                                               u64& mlo, u64& mhi) {
    float h1[8];
    enc01h(s, w, h1);
    mlo = 0ull; mhi = 0ull;
#pragma unroll 4
    for (int m = 0; m < 128; m += 4) {
        float4 a = make_float4(0.f, 0.f, 0.f, 0.f);
#pragma unroll
        for (int j = 0; j < 8; j++) {
            float4 ww = *(const float4*)&w[EW2 + j * 128 + m];
            a.x = fmaf(h1[j], ww.x, a.x);
            a.y = fmaf(h1[j], ww.y, a.y);
            a.z = fmaf(h1[j], ww.z, a.z);
            a.w = fmaf(h1[j], ww.w, a.w);
        }
        a.x += w[EB2 + m + 0];
        a.y += w[EB2 + m + 1];
        a.z += w[EB2 + m + 2];
        a.w += w[EB2 + m + 3];
        unsigned bits = 0;
        float4 o;
        if (a.x < 0.1f) { o.x = 0.f; } else { o.x = 1.f; bits |= 1u; }
        if (a.y < 0.1f) { o.y = 0.f; } else { o.y = 1.f; bits |= 2u; }
        if (a.z < 0.1f) { o.z = 0.f; } else { o.z = 1.f; bits |= 4u; }
        if (a.w < 0.1f) { o.w = 0.f; } else { o.w = 1.f; bits |= 8u; }
        if (m < 64) mlo |= (u64)bits << m;
        else        mhi |= (u64)bits << (m - 64);
        *(float4*)&dst[m] = o;
    }
}

// ---------------------------------------------------------------------------
// Paired head (verified; x as packed register pairs)
// ---------------------------------------------------------------------------
__device__ __forceinline__ void head_fn2r(const u64* __restrict__ xa,
                                          const u64* __restrict__ xb,
                                          const float* __restrict__ w1t,
                                          const float* __restrict__ b1,
                                          const float* __restrict__ w2,
                                          const float* __restrict__ b2,
                                          float* __restrict__ dsta,
                                          float* __restrict__ dstb) {
    const ulonglong2* b2p = (const ulonglong2*)b2;
    ulonglong2 b2lo = b2p[0], b2hi = b2p[1];
    u64 oa0 = b2lo.x, oa1 = b2lo.y, oa2 = b2hi.x, oa3 = b2hi.y;
    u64 ob0 = oa0, ob1 = oa1, ob2 = oa2, ob3 = oa3;
    const ulonglong2* w1p = (const ulonglong2*)w1t;
    const ulonglong2* w2p = (const ulonglong2*)w2;
#pragma unroll 4
    for (int j = 0; j < 128; j++) {
        ulonglong2 wA = w1p[j * 2];
        ulonglong2 wB = w1p[j * 2 + 1];
        float bj = b1[j];
        u64 a0 = ffma2u(xa[0], wA.x, 0ull);
        u64 a1 = ffma2u(xa[2], wB.x, 0ull);
        a0 = ffma2u(xa[1], wA.y, a0);
        a1 = ffma2u(xa[3], wB.y, a1);
        u64 c0 = ffma2u(xb[0], wA.x, 0ull);
        u64 c1 = ffma2u(xb[2], wB.x, 0ull);
        c0 = ffma2u(xb[1], wA.y, c0);
        c1 = ffma2u(xb[3], wB.y, c1);
        float a0x, a0y, a1x, a1y, c0x, c0y, c1x, c1y;
        upk2(a0, a0x, a0y); upk2(a1, a1x, a1y);
        upk2(c0, c0x, c0y); upk2(c1, c1x, c1y);
        float ha = a0x + a0y + a1x + a1y + bj;
        float hb = c0x + c0y + c1x + c1y + bj;
        ha = fmaxf(ha, 0.f);
        hb = fmaxf(hb, 0.f);
        u64 hha = pk2(ha, ha);
        u64 hhb = pk2(hb, hb);
        ulonglong2 u = w2p[j * 2];
        ulonglong2 v = w2p[j * 2 + 1];
        oa0 = ffma2u(hha, u.x, oa0); oa1 = ffma2u(hha, u.y, oa1);
        oa2 = ffma2u(hha, v.x, oa2); oa3 = ffma2u(hha, v.y, oa3);
        ob0 = ffma2u(hhb, u.x, ob0); ob1 = ffma2u(hhb, u.y, ob1);
        ob2 = ffma2u(hhb, v.x, ob2); ob3 = ffma2u(hhb, v.y, ob3);
    }
    ulonglong2* da = (ulonglong2*)dsta;
    ulonglong2* db = (ulonglong2*)dstb;
    da[0] = make_ulonglong2(oa0, oa1);
    da[1] = make_ulonglong2(oa2, oa3);
    db[0] = make_ulonglong2(ob0, ob1);
    db[1] = make_ulonglong2(ob2, ob3);
}

// ---------------------------------------------------------------------------
// Fused kernel. A staging layout: [row][c4][half][kt4], row stride 36 floats.
// W fragment-major (copied from g_wf). All fragment loads are LDS.128 with
// linear addressing — no XOR swizzle math.
// ---------------------------------------------------------------------------
#define DB 256
#define DGRID (T_LEN / 128)   // 1024
#define AROW 36

// smem float offsets
#define SD_A    0                       // 256 * 36 = 9216
#define SD_W    9216                    // 2048
#define SD_BW   11264                   // 2048
#define SD_BEFF 13312                   // 16
#define E_C     13328
#define E_P     (E_C + ESZ)             // 14568
#define E_MW1T  (E_P + ESZ)             // 15808
#define E_MB1   (E_MW1T + 1024)
#define E_MW2   (E_MB1 + 128)
#define E_MB2   (E_MW2 + 1024)
#define E_VW1T  (E_MB2 + 8)
#define E_VB1   (E_VW1T + 1024)
#define E_VW2   (E_VB1 + 128)
#define E_VB2   (E_VW2 + 1024)
#define SD_TOT  (E_VB2 + 8)             // 20176
#define FUSED_SMEM_BYTES (SD_TOT * 4)   // 80704 B -> 2 CTA/SM

__global__ __launch_bounds__(DB, 2)
void fused_kernel(const float* __restrict__ lm, const float* __restrict__ lv,
                  const float* __restrict__ Tin,
                  const float* cw0, const float* cb0, const float* cw1,
                  const float* cb1, const float* cw2, const float* cb2,
                  const float* pw0, const float* pb0, const float* pw1,
                  const float* pb1, const float* pw2, const float* pb2,
                  const float* fmw1, const float* fmb1,
                  const float* fmw2, const float* fmb2,
                  const float* fvw1, const float* fvb1,
                  const float* fvw2, const float* fvb2,
                  const float* __restrict__ lb0, float* __restrict__ out) {
    extern __shared__ __align__(16) float smem[];
    const int tid = threadIdx.x;
    const int warp = tid >> 5;
    const int lane = tid & 31;
    const int t0 = blockIdx.x * 128;
    const bool isRecon = tid < 128;
    const int rr = isRecon ? tid : tid - 128;
    const size_t tl = (size_t)t0 + rr;

    // ---- cooperative smem fill ----
    for (int i = tid; i < ESZ; i += DB) {
        float v, u;
        if (i < 8)         { v = cw0[i];        u = pw0[i];        }
        else if (i < 16)   { v = cb0[i - 8];    u = pb0[i - 8];    }
        else if (i < 80)   { v = cw1[i - 16];   u = pw1[i - 16];   }
        else if (i < 88)   { v = cb1[i - 80];   u = pb1[i - 80];   }
        else if (i < 1112) { v = cw2[i - 88];   u = pw2[i - 88];   }
        else               { v = cb2[i - 1112]; u = pb2[i - 1112]; }
        smem[E_C + i] = v;
        smem[E_P + i] = u;
    }
    for (int i = tid; i < 1024; i += DB) {
        int j = i >> 3, k = i & 7;
        smem[E_MW1T + i] = fmw1[k * 128 + j];
        smem[E_VW1T + i] = fvw1[k * 128 + j];
        smem[E_MW2 + i]  = fmw2[i];
        smem[E_VW2 + i]  = fvw2[i];
        smem[SD_BW + 2 * i]     = lb0[i];
        smem[SD_BW + 2 * i + 1] = g_w12[i];
    }
    if (tid < 128) { smem[E_MB1 + tid] = fmb1[tid]; smem[E_VB1 + tid] = fvb1[tid]; }
    if (tid < 8)   { smem[E_MB2 + tid] = fmb2[tid]; smem[E_VB2 + tid] = fvb2[tid]; }
    if (tid < 16)  smem[SD_BEFF + tid] = g_beff[tid];
    __syncthreads();

    // ---- latents register-resident (raw fp32 for enc/head phase) ----
    float lat[32];
    {
        const float4* lm4 = (const float4*)lm;
        const float4* lv4 = (const float4*)lv;
        float4 a0 = lm4[tl * 2], a1 = lm4[tl * 2 + 1];
        float4 b0 = lm4[((size_t)T_LEN + tl) * 2], b1 = lm4[((size_t)T_LEN + tl) * 2 + 1];
        float4 c0 = lv4[tl * 2], c1 = lv4[tl * 2 + 1];
        float4 d0 = lv4[((size_t)T_LEN + tl) * 2], d1 = lv4[((size_t)T_LEN + tl) * 2 + 1];
        float M0[8] = {a0.x, a0.y, a0.z, a0.w, a1.x, a1.y, a1.z, a1.w};
        float M1[8] = {b0.x, b0.y, b0.z, b0.w, b1.x, b1.y, b1.z, b1.w};
        float V0[8] = {c0.x, c0.y, c0.z, c0.w, c1.x, c1.y, c1.z, c1.w};
        float V1[8] = {d0.x, d0.y, d0.z, d0.w, d1.x, d1.y, d1.z, d1.w};
#pragma unroll
        for (int k = 0; k < 8; k++) {
            lat[2 * k]     = M0[k];
            lat[2 * k + 1] = M1[k];
            lat[16 + 2 * k]     = V0[k];
            lat[16 + 2 * k + 1] = V1[k];
        }
    }

    // ---- enc phase ----
    u64 mlo = 0ull, mhi = 0ull;
    if (isRecon) {
        float s = Tin[tl];
        enc_branch_bin(s, smem + E_C, out + OFF_CT + tl * 128, mlo, mhi);
        if (t0 == 0 && tid == 0)
            enc_branch_cont(Tin[0], smem + E_P, out + OFF_CT1);
    } else {
        size_t tt = tl + 1;
        if (tt < T_LEN)
            enc_branch_cont(Tin[tt], smem + E_P, out + OFF_CT1 + tt * 128);
    }

    // ---- head phase ----
    {
        u64 xa[4], xb[4];
        int base = isRecon ? 0 : 16;
#pragma unroll
        for (int i = 0; i < 4; i++) {
            xa[i] = pk2(lat[base + 4 * i], lat[base + 4 * i + 2]);
            xb[i] = pk2(lat[base + 4 * i + 1], lat[base + 4 * i + 3]);
        }
        const float* w1t = isRecon ? smem + E_MW1T : smem + E_VW1T;
        const float* b1h = isRecon ? smem + E_MB1  : smem + E_VB1;
        const float* w2h = isRecon ? smem + E_MW2  : smem + E_VW2;
        const float* b2h = isRecon ? smem + E_MB2  : smem + E_VB2;
        float* hdst = out + (isRecon ? OFF_LMP : OFF_LVP);
        head_fn2r(xa, xb, w1t, b1h, w2h, b2h,
                  hdst + tl * 8, hdst + ((size_t)T_LEN + tl) * 8);
    }

    // recon lat -> tf32
    if (isRecon) {
#pragma unroll
        for (int i = 0; i < 32; i++) lat[i] = cvt_tf32(lat[i]);
    }

    // ---- decode node loop ----
    for (int n = 0; n < D_X; n++) {
        // W_n fragment-major copy (linear)
        for (int i = tid; i < 512; i += DB)
            ((float4*)(smem + SD_W))[i] = ((const float4*)(g_wf + n * 2048))[i];

        // staging A
        {
            float f[32];
            if (isRecon) {
                unsigned byte = (unsigned)((n < 8 ? (mlo >> (8 * n))
                                                  : (mhi >> (8 * (n - 8)))) & 0xffu);
#pragma unroll
                for (int k = 0; k < 8; k++) {
                    bool on = (byte >> k) & 1u;
                    f[2 * k]     = on ? lat[2 * k] : 0.f;
                    f[2 * k + 1] = on ? lat[2 * k + 1] : 0.f;
                    f[16 + 2 * k]     = on ? lat[16 + 2 * k] : 0.f;
                    f[16 + 2 * k + 1] = on ? lat[16 + 2 * k + 1] : 0.f;
                }
            } else {
                size_t tt = tl + 1;
                float cp[8];
                if (tt < T_LEN) {
                    const float4* c4p = (const float4*)(out + OFF_CT1 + tt * 128 + n * 8);
                    float4 ca = c4p[0], cb = c4p[1];
                    cp[0] = ca.x; cp[1] = ca.y; cp[2] = ca.z; cp[3] = ca.w;
                    cp[4] = cb.x; cp[5] = cb.y; cp[6] = cb.z; cp[7] = cb.w;
                } else {
#pragma unroll
                    for (int k = 0; k < 8; k++) cp[k] = 0.f;
                }
#pragma unroll
                for (int k = 0; k < 8; k++) {
                    f[2 * k]     = cvt_tf32(cp[k] * lat[2 * k]);
                    f[2 * k + 1] = cvt_tf32(cp[k] * lat[2 * k + 1]);
                    f[16 + 2 * k]     = cvt_tf32(cp[k] * lat[16 + 2 * k]);
                    f[16 + 2 * k + 1] = cvt_tf32(cp[k] * lat[16 + 2 * k + 1]);
                }
            }
            // store [row][c4][half][kt4], row stride 36
            float* arow = smem + SD_A + tid * AROW;
#pragma unroll
            for (int c4 = 0; c4 < 4; c4++) {
#pragma unroll
                for (int h = 0; h < 2; h++) {
                    float4 v = make_float4(f[h * 4 + c4], f[8 + h * 4 + c4],
                                           f[16 + h * 4 + c4], f[24 + h * 4 + c4]);
                    *(float4*)&arow[c4 * 8 + h * 4] = v;
                }
            }
        }
        __syncthreads();

        const int m0w = warp * 32;
        float sums[2][2] = {{0.f, 0.f}, {0.f, 0.f}};

        // A fragments: 8 LDS.128, linear addresses
        unsigned afr[2][4][4];
#pragma unroll
        for (int mt = 0; mt < 2; mt++) {
            int ra = m0w + mt * 16 + (lane >> 2);
            int rb = ra + 8;
            const float* pra = smem + SD_A + ra * AROW + (lane & 3) * 8;
            const float* prb = smem + SD_A + rb * AROW + (lane & 3) * 8;
            float4 qa0 = *(const float4*)pra;
            float4 qa1 = *(const float4*)(pra + 4);
            float4 qb0 = *(const float4*)prb;
            float4 qb1 = *(const float4*)(prb + 4);
            const float* a0 = (const float*)&qa0;
            const float* b0 = (const float*)&qb0;
            const float* a1 = (const float*)&qa1;
            const float* b1 = (const float*)&qb1;
#pragma unroll
            for (int kt = 0; kt < 4; kt++) {
                afr[mt][kt][0] = __float_as_uint(a0[kt]);
                afr[mt][kt][1] = __float_as_uint(b0[kt]);
                afr[mt][kt][2] = __float_as_uint(a1[kt]);
                afr[mt][kt][3] = __float_as_uint(b1[kt]);
            }
        }

        for (int nh = 0; nh < 2; nh++) {
            const float* SWb = smem + SD_W + nh * 1024;
#pragma unroll
            for (int nt = 0; nt < 4; nt++) {
                float4 q0 = *(const float4*)&SWb[(nt * 64 + lane) * 4];
                float4 q1 = *(const float4*)&SWb[(nt * 64 + 32 + lane) * 4];
                const float* w0 = (const float*)&q0;
                const float* w1 = (const float*)&q1;
                int j0 = nh * 32 + nt * 8 + (lane & 3) * 2;
                float4 bw2 = *(const float4*)&smem[SD_BW + (n * 64 + j0) * 2];
#pragma unroll
                for (int mt = 0; mt < 2; mt++) {
                    float cfr[4] = {0.f, 0.f, 0.f, 0.f};
#pragma unroll
                    for (int kt = 0; kt < 4; kt++) {
                        unsigned bb[2] = {__float_as_uint(w0[kt]),
                                          __float_as_uint(w1[kt])};
                        mma_tf32(cfr, afr[mt][kt], bb);
                    }
                    sums[mt][0] += fmaxf(cfr[0] + bw2.x, 0.f) * bw2.y +
                                   fmaxf(cfr[1] + bw2.z, 0.f) * bw2.w;
                    sums[mt][1] += fmaxf(cfr[2] + bw2.x, 0.f) * bw2.y +
                                   fmaxf(cfr[3] + bw2.z, 0.f) * bw2.w;
                }
            }
        }

        float be = smem[SD_BEFF + n];
#pragma unroll
        for (int mt = 0; mt < 2; mt++) {
#pragma unroll
            for (int h = 0; h < 2; h++) {
                float v = sums[mt][h];
                v += __shfl_xor_sync(0xffffffffu, v, 1);
                v += __shfl_xor_sync(0xffffffffu, v, 2);
                if ((lane & 3) == 0) {
                    int row = m0w + mt * 16 + h * 8 + (lane >> 2);
                    float val = fmaxf(v + be, 0.f);
                    if (row < 128) {
                        out[OFF_RECON + (size_t)(t0 + row) * 16 + n] = val;
                    } else {
                        size_t tt = (size_t)t0 + (row - 128) + 1;
                        if (tt < T_LEN)
                            out[OFF_PRED + tt * 16 + n] = val;
                    }
                }
            }
        }
        __syncthreads();
    }
}

// ---------------------------------------------------------------------------
extern "C" void kernel_launch(void* const* d_in, const int* in_sizes, int n_in,
                              void* d_out, int out_size) {
    const float* lm  = (const float*)d_in[0];
    const float* lv  = (const float*)d_in[1];
    const float* Tin = (const float*)d_in[2];
    const float* cw0 = (const float*)d_in[3];
    const float* cb0 = (const float*)d_in[4];
    const float* cw1 = (const float*)d_in[5];
    const float* cb1 = (const float*)d_in[6];
    const float* cw2 = (const float*)d_in[7];
    const float* cb2 = (const float*)d_in[8];
    const float* pw0 = (const float*)d_in[9];
    const float* pb0 = (const float*)d_in[10];
    const float* pw1 = (const float*)d_in[11];
    const float* pb1 = (const float*)d_in[12];
    const float* pw2 = (const float*)d_in[13];
    const float* pb2 = (const float*)d_in[14];
    const float* fmw1 = (const float*)d_in[15];
    const float* fmb1 = (const float*)d_in[16];
    const float* fmw2 = (const float*)d_in[17];
    const float* fmb2 = (const float*)d_in[18];
    const float* fvw1 = (const float*)d_in[19];
    const float* fvb1 = (const float*)d_in[20];
    const float* fvw2 = (const float*)d_in[21];
    const float* fvb2 = (const float*)d_in[22];
    const float* lw0 = (const float*)d_in[23];
    const float* lb0 = (const float*)d_in[24];
    const float* lw1 = (const float*)d_in[25];
    const float* lb1 = (const float*)d_in[26];
    const float* lw2 = (const float*)d_in[27];
    const float* lb2 = (const float*)d_in[28];
    float* out = (float*)d_out;

    cudaFuncSetAttribute(fused_kernel, cudaFuncAttributeMaxDynamicSharedMemorySize,
                         FUSED_SMEM_BYTES);

    prep_kernel<<<16, 256>>>(lw0, lw1, lw2, lb0, lb1, lb2, out);
    fused_kernel<<<DGRID, DB, FUSED_SMEM_BYTES>>>(
        lm, lv, Tin,
        cw0, cb0, cw1, cb1, cw2, cb2,
        pw0, pb0, pw1, pb1, pw2, pb2,
        fmw1, fmb1, fmw2, fmb2,
        fvw1, fvb1, fvw2, fvb2,
        lb0, out);
}

// round 14
// speedup vs baseline: 1.1344x; 1.1344x over previous
#include <cuda_runtime.h>
#include <cstdint>

#define T_LEN 131072
#define D_X 16
#define D_L 8

// d_out layout (flat concat of reference tuple, all float32)
#define OFF_RECON 0
#define OFF_PRED  (T_LEN * D_X)
#define OFF_LMP   (2 * T_LEN * D_X)
#define OFF_LVP   (OFF_LMP + 2 * T_LEN * D_L)
#define OFF_CT    (OFF_LVP + 2 * T_LEN * D_L)
#define OFF_CT1   (OFF_CT + T_LEN * D_X * D_L)

typedef unsigned long long u64;

// ---------------------------------------------------------------------------
// Packed fp32x2 helpers (verified head path)
// ---------------------------------------------------------------------------
__device__ __forceinline__ u64 pk2(float x, float y) {
    u64 r;
    asm("mov.b64 %0, {%1, %2};" : "=l"(r) : "f"(x), "f"(y));
    return r;
}
__device__ __forceinline__ void upk2(u64 a, float& x, float& y) {
    asm("mov.b64 {%0, %1}, %2;" : "=f"(x), "=f"(y) : "l"(a));
}
__device__ __forceinline__ u64 ffma2u(u64 a, u64 b, u64 c) {
    u64 d;
    asm("fma.rn.f32x2 %0, %1, %2, %3;" : "=l"(d) : "l"(a), "l"(b), "l"(c));
    return d;
}

// tf32 conversion + mma
__device__ __forceinline__ float cvt_tf32(float x) {
    float r;
    asm("cvt.rna.tf32.f32 %0, %1;" : "=f"(r) : "f"(x));
    return r;
}
__device__ __forceinline__ void mma_tf32(float* c, const unsigned* a,
                                         const unsigned* b) {
    asm volatile(
        "mma.sync.aligned.m16n8k8.row.col.f32.tf32.tf32.f32 "
        "{%0,%1,%2,%3}, {%4,%5,%6,%7}, {%8,%9}, {%0,%1,%2,%3};"
        : "+f"(c[0]), "+f"(c[1]), "+f"(c[2]), "+f"(c[3])
        : "r"(a[0]), "r"(a[1]), "r"(a[2]), "r"(a[3]), "r"(b[0]), "r"(b[1]));
}

// ---------------------------------------------------------------------------
// Device-global scratch (no allocation).
// ---------------------------------------------------------------------------
__device__ __align__(16) float g_w0t[D_X * 64 * 32];  // [n][j][f], tf32
__device__ __align__(16) float g_w12[D_X * 64];       // collapsed lw1@lw2
__device__ __align__(16) float g_beff[D_X];           // lb1@lw2 + lb2

// grid = 16 (one CTA per node), block = 256
__global__ void prep_kernel(const float* __restrict__ lw0,
                            const float* __restrict__ lw1,
                            const float* __restrict__ lw2,
                            const float* __restrict__ lb0,
                            const float* __restrict__ lb1,
                            const float* __restrict__ lb2,
                            float* __restrict__ out) {
    int n = blockIdx.x;
    int tid = threadIdx.x;
    int j = tid & 63;
    int q = tid >> 6;
#pragma unroll
    for (int ff = 0; ff < 8; ff++) {
        int f = q * 8 + ff;
        g_w0t[(n * 64 + j) * 32 + f] = cvt_tf32(lw0[(n * 32 + f) * 64 + j]);
    }
    if (q == 0) {
        float acc = 0.f;
#pragma unroll 8
        for (int o = 0; o < 64; o++)
            acc = fmaf(lw1[(n * 64 + j) * 64 + o], lw2[n * 64 + o], acc);
        g_w12[n * 64 + j] = acc;
        if (j == 0) {
            float b = lb2[n];
            for (int o = 0; o < 64; o++)
                b = fmaf(lb1[n * 64 + o], lw2[n * 64 + o], b);
            g_beff[n] = b;
        }
    }
    __syncthreads();
    if (tid == 0) {
        float s = g_beff[n];
        for (int o = 0; o < 64; o++) {
            float h = fmaxf(lb0[n * 64 + o], 0.f);
            s = fmaf(h, g_w12[n * 64 + o], s);
        }
        out[OFF_PRED + n] = fmaxf(s, 0.f);
    }
}

// ---------------------------------------------------------------------------
// Encoder (verified round-2 arithmetic): packed smem block per branch.
// ---------------------------------------------------------------------------
#define EW0 0
#define EB0 8
#define EW1 16
#define EB1 80
#define EW2 88
#define EB2 1112
#define ESZ 1240

__device__ __forceinline__ void enc01h(float s, const float* __restrict__ w,
                                       float* __restrict__ h1) {
    float h0[8];
#pragma unroll
    for (int i = 0; i < 8; i++) {
        float v = fmaf(s, w[EW0 + i], w[EB0 + i]);
        h0[i] = v > 0.f ? v : 0.01f * v;
    }
#pragma unroll
    for (int j = 0; j < 8; j++) {
        float a = 0.f;
#pragma unroll
        for (int i = 0; i < 8; i++) a = fmaf(h0[i], w[EW1 + i * 8 + j], a);
        a += w[EB1 + j];
        h1[j] = a > 0.f ? a : 0.01f * a;
    }
}

__device__ __forceinline__ void enc_branch_cont(float s, const float* __restrict__ w,
                                                float* __restrict__ dst) {
    float h1[8];
    enc01h(s, w, h1);
#pragma unroll 4
    for (int m = 0; m < 128; m += 4) {
        float4 a = make_float4(0.f, 0.f, 0.f, 0.f);
#pragma unroll
        for (int j = 0; j < 8; j++) {
            float4 ww = *(const float4*)&w[EW2 + j * 128 + m];
            a.x = fmaf(h1[j], ww.x, a.x);
            a.y = fmaf(h1[j], ww.y, a.y);
            a.z = fmaf(h1[j], ww.z, a.z);
            a.w = fmaf(h1[j], ww.w, a.w);
        }
        a.x += w[EB2 + m + 0];
        a.y += w[EB2 + m + 1];
        a.z += w[EB2 + m + 2];
        a.w += w[EB2 + m + 3];
        *(float4*)&dst[m] = a;
    }
}

__device__ __forceinline__ void enc_branch_bin(float s, const float* __restrict__ w,
                                               float* __restrict__ dst,
                                               u64& mlo, u64& mhi) {
    float h1[8];
    enc01h(s, w, h1);
    mlo = 0ull; mhi = 0ull;
#pragma unroll 4
    for (int m = 0; m < 128; m += 4) {
        float4 a = make_float4(0.f, 0.f, 0.f, 0.f);
#pragma unroll
        for (int j = 0; j < 8; j++) {
            float4 ww = *(const float4*)&w[EW2 + j * 128 + m];
            a.x = fmaf(h1[j], ww.x, a.x);
            a.y = fmaf(h1[j], ww.y, a.y);
            a.z = fmaf(h1[j], ww.z, a.z);
            a.w = fmaf(h1[j], ww.w, a.w);
        }
        a.x += w[EB2 + m + 0];
        a.y += w[EB2 + m + 1];
        a.z += w[EB2 + m + 2];
        a.w += w[EB2 + m + 3];
        unsigned bits = 0;
        float4 o;
        if (a.x < 0.1f) { o.x = 0.f; } else { o.x = 1.f; bits |= 1u; }
        if (a.y < 0.1f) { o.y = 0.f; } else { o.y = 1.f; bits |= 2u; }
        if (a.z < 0.1f) { o.z = 0.f; } else { o.z = 1.f; bits |= 4u; }
        if (a.w < 0.1f) { o.w = 0.f; } else { o.w = 1.f; bits |= 8u; }
        if (m < 64) mlo |= (u64)bits << m;
        else        mhi |= (u64)bits << (m - 64);
        *(float4*)&dst[m] = o;
    }
}

// ---------------------------------------------------------------------------
// Paired head (verified; x as packed register pairs)
// ---------------------------------------------------------------------------
__device__ __forceinline__ void head_fn2r(const u64* __restrict__ xa,
                                          const u64* __restrict__ xb,
                                          const float* __restrict__ w1t,
                                          const float* __restrict__ b1,
                                          const float* __restrict__ w2,
                                          const float* __restrict__ b2,
                                          float* __restrict__ dsta,
                                          float* __restrict__ dstb) {
    const ulonglong2* b2p = (const ulonglong2*)b2;
    ulonglong2 b2lo = b2p[0], b2hi = b2p[1];
    u64 oa0 = b2lo.x, oa1 = b2lo.y, oa2 = b2hi.x, oa3 = b2hi.y;
    u64 ob0 = oa0, ob1 = oa1, ob2 = oa2, ob3 = oa3;
    const ulonglong2* w1p = (const ulonglong2*)w1t;
    const ulonglong2* w2p = (const ulonglong2*)w2;
#pragma unroll 4
    for (int j = 0; j < 128; j++) {
        ulonglong2 wA = w1p[j * 2];
        ulonglong2 wB = w1p[j * 2 + 1];
        float bj = b1[j];
        u64 a0 = ffma2u(xa[0], wA.x, 0ull);
        u64 a1 = ffma2u(xa[2], wB.x, 0ull);
        a0 = ffma2u(xa[1], wA.y, a0);
        a1 = ffma2u(xa[3], wB.y, a1);
        u64 c0 = ffma2u(xb[0], wA.x, 0ull);
        u64 c1 = ffma2u(xb[2], wB.x, 0ull);
        c0 = ffma2u(xb[1], wA.y, c0);
        c1 = ffma2u(xb[3], wB.y, c1);
        float a0x, a0y, a1x, a1y, c0x, c0y, c1x, c1y;
        upk2(a0, a0x, a0y); upk2(a1, a1x, a1y);
        upk2(c0, c0x, c0y); upk2(c1, c1x, c1y);
        float ha = a0x + a0y + a1x + a1y + bj;
        float hb = c0x + c0y + c1x + c1y + bj;
        ha = fmaxf(ha, 0.f);
        hb = fmaxf(hb, 0.f);
        u64 hha = pk2(ha, ha);
        u64 hhb = pk2(hb, hb);
        ulonglong2 u = w2p[j * 2];
        ulonglong2 v = w2p[j * 2 + 1];
        oa0 = ffma2u(hha, u.x, oa0); oa1 = ffma2u(hha, u.y, oa1);
        oa2 = ffma2u(hha, v.x, oa2); oa3 = ffma2u(hha, v.y, oa3);
        ob0 = ffma2u(hhb, u.x, ob0); ob1 = ffma2u(hhb, u.y, ob1);
        ob2 = ffma2u(hhb, v.x, ob2); ob3 = ffma2u(hhb, v.y, ob3);
    }
    ulonglong2* da = (ulonglong2*)dsta;
    ulonglong2* db = (ulonglong2*)dstb;
    da[0] = make_ulonglong2(oa0, oa1);
    da[1] = make_ulonglong2(oa2, oa3);
    db[0] = make_ulonglong2(ob0, ob1);
    db[1] = make_ulonglong2(ob2, ob3);
}

// ---------------------------------------------------------------------------
// Fused kernel (R12 structure; hoisted swizzle offsets + bw2).
// ---------------------------------------------------------------------------
#define DB 256
#define DGRID (T_LEN / 128)   // 1024

// smem float offsets
#define SD_A    0                 // 256 x 32, chunk-XOR swizzle : 8192
#define SD_W    8192              // 64 x 32 (tf32), swizzle : 2048
#define SD_BW   10240             // [n][j] (b0, w12) pairs : 2048
#define SD_BEFF 12288             // 16
#define E_C     12304             // 1240
#define E_P     (E_C + ESZ)
#define E_MW1T  (E_P + ESZ)
#define E_MB1   (E_MW1T + 1024)
#define E_MW2   (E_MB1 + 128)
#define E_MB2   (E_MW2 + 1024)
#define E_VW1T  (E_MB2 + 8)
#define E_VB1   (E_VW1T + 1024)
#define E_VW2   (E_VB1 + 128)
#define E_VB2   (E_VW2 + 1024)
#define SD_TOT  (E_VB2 + 8)       // 19152
#define FUSED_SMEM_BYTES (SD_TOT * 4)   // 76608 B -> 2 CTA/SM

__global__ __launch_bounds__(DB, 2)
void fused_kernel(const float* __restrict__ lm, const float* __restrict__ lv,
                  const float* __restrict__ Tin,
                  const float* cw0, const float* cb0, const float* cw1,
                  const float* cb1, const float* cw2, const float* cb2,
                  const float* pw0, const float* pb0, const float* pw1,
                  const float* pb1, const float* pw2, const float* pb2,
                  const float* fmw1, const float* fmb1,
                  const float* fmw2, const float* fmb2,
                  const float* fvw1, const float* fvb1,
                  const float* fvw2, const float* fvb2,
                  const float* __restrict__ lb0, float* __restrict__ out) {
    extern __shared__ __align__(16) float smem[];
    const int tid = threadIdx.x;
    const int warp = tid >> 5;
    const int lane = tid & 31;
    const int t0 = blockIdx.x * 128;
    const bool isRecon = tid < 128;
    const int rr = isRecon ? tid : tid - 128;
    const size_t tl = (size_t)t0 + rr;

    // ---- cooperative smem fill ----
    for (int i = tid; i < ESZ; i += DB) {
        float v, u;
        if (i < 8)         { v = cw0[i];        u = pw0[i];        }
        else if (i < 16)   { v = cb0[i - 8];    u = pb0[i - 8];    }
        else if (i < 80)   { v = cw1[i - 16];   u = pw1[i - 16];   }
        else if (i < 88)   { v = cb1[i - 80];   u = pb1[i - 80];   }
        else if (i < 1112) { v = cw2[i - 88];   u = pw2[i - 88];   }
        else               { v = cb2[i - 1112]; u = pb2[i - 1112]; }
        smem[E_C + i] = v;
        smem[E_P + i] = u;
    }
    for (int i = tid; i < 1024; i += DB) {
        int j = i >> 3, k = i & 7;
        smem[E_MW1T + i] = fmw1[k * 128 + j];
        smem[E_VW1T + i] = fvw1[k * 128 + j];
        smem[E_MW2 + i]  = fmw2[i];
        smem[E_VW2 + i]  = fvw2[i];
        smem[SD_BW + 2 * i]     = lb0[i];
        smem[SD_BW + 2 * i + 1] = g_w12[i];
    }
    if (tid < 128) { smem[E_MB1 + tid] = fmb1[tid]; smem[E_VB1 + tid] = fvb1[tid]; }
    if (tid < 8)   { smem[E_MB2 + tid] = fmb2[tid]; smem[E_VB2 + tid] = fvb2[tid]; }
    if (tid < 16)  smem[SD_BEFF + tid] = g_beff[tid];
    __syncthreads();

    // ---- latents register-resident (raw fp32 for enc/head phase) ----
    float lat[32];
    {
        const float4* lm4 = (const float4*)lm;
        const float4* lv4 = (const float4*)lv;
        float4 a0 = lm4[tl * 2], a1 = lm4[tl * 2 + 1];
        float4 b0 = lm4[((size_t)T_LEN + tl) * 2], b1 = lm4[((size_t)T_LEN + tl) * 2 + 1];
        float4 c0 = lv4[tl * 2], c1 = lv4[tl * 2 + 1];
        float4 d0 = lv4[((size_t)T_LEN + tl) * 2], d1 = lv4[((size_t)T_LEN + tl) * 2 + 1];
        float M0[8] = {a0.x, a0.y, a0.z, a0.w, a1.x, a1.y, a1.z, a1.w};
        float M1[8] = {b0.x, b0.y, b0.z, b0.w, b1.x, b1.y, b1.z, b1.w};
        float V0[8] = {c0.x, c0.y, c0.z, c0.w, c1.x, c1.y, c1.z, c1.w};
        float V1[8] = {d0.x, d0.y, d0.z, d0.w, d1.x, d1.y, d1.z, d1.w};
#pragma unroll
        for (int k = 0; k < 8; k++) {
            lat[2 * k]     = M0[k];
            lat[2 * k + 1] = M1[k];
            lat[16 + 2 * k]     = V0[k];
            lat[16 + 2 * k + 1] = V1[k];
        }
    }

    // ---- enc phase ----
    u64 mlo = 0ull, mhi = 0ull;
    if (isRecon) {
        float s = Tin[tl];
        enc_branch_bin(s, smem + E_C, out + OFF_CT + tl * 128, mlo, mhi);
        if (t0 == 0 && tid == 0)
            enc_branch_cont(Tin[0], smem + E_P, out + OFF_CT1);
    } else {
        size_t tt = tl + 1;
        if (tt < T_LEN)
            enc_branch_cont(Tin[tt], smem + E_P, out + OFF_CT1 + tt * 128);
    }

    // ---- head phase ----
    {
        u64 xa[4], xb[4];
        int base = isRecon ? 0 : 16;
#pragma unroll
        for (int i = 0; i < 4; i++) {
            xa[i] = pk2(lat[base + 4 * i], lat[base + 4 * i + 2]);
            xb[i] = pk2(lat[base + 4 * i + 1], lat[base + 4 * i + 3]);
        }
        const float* w1t = isRecon ? smem + E_MW1T : smem + E_VW1T;
        const float* b1h = isRecon ? smem + E_MB1  : smem + E_VB1;
        const float* w2h = isRecon ? smem + E_MW2  : smem + E_VW2;
        const float* b2h = isRecon ? smem + E_MB2  : smem + E_VB2;
        float* hdst = out + (isRecon ? OFF_LMP : OFF_LVP);
        head_fn2r(xa, xb, w1t, b1h, w2h, b2h,
                  hdst + tl * 8, hdst + ((size_t)T_LEN + tl) * 8);
    }

    // recon lat -> tf32
    if (isRecon) {
#pragma unroll
        for (int i = 0; i < 32; i++) lat[i] = cvt_tf32(lat[i]);
    }

    // precomputed per-thread swizzle column offsets (constant across nodes):
    // for rows ra,rb and weight rows j used by this lane, row&7 == lane>>2,
    // so offset[k2] = ((k2 ^ (lane>>2)) << 2) + (lane & 3).
    int col[8];
#pragma unroll
    for (int k2 = 0; k2 < 8; k2++)
        col[k2] = (((k2 ^ (lane >> 2)) << 2) + (lane & 3));

    // ---- decode node loop (R12 structure) ----
    for (int n = 0; n < D_X; n++) {
        for (int i = tid; i < 512; i += DB) {
            int j = i >> 3, ch = i & 7;
            float4 w = ((const float4*)(g_w0t + n * 2048))[i];
            *(float4*)&smem[SD_W + j * 32 + ((ch ^ (j & 7)) << 2)] = w;
        }
        {
            float f[32];
            if (isRecon) {
                unsigned byte = (unsigned)((n < 8 ? (mlo >> (8 * n))
                                                  : (mhi >> (8 * (n - 8)))) & 0xffu);
#pragma unroll
                for (int k = 0; k < 8; k++) {
                    bool on = (byte >> k) & 1u;
                    f[2 * k]     = on ? lat[2 * k] : 0.f;
                    f[2 * k + 1] = on ? lat[2 * k + 1] : 0.f;
                    f[16 + 2 * k]     = on ? lat[16 + 2 * k] : 0.f;
                    f[16 + 2 * k + 1] = on ? lat[16 + 2 * k + 1] : 0.f;
                }
            } else {
                size_t tt = tl + 1;
                float cp[8];
                if (tt < T_LEN) {
                    const float4* c4 = (const float4*)(out + OFF_CT1 + tt * 128 + n * 8);
                    float4 ca = c4[0], cb = c4[1];
                    cp[0] = ca.x; cp[1] = ca.y; cp[2] = ca.z; cp[3] = ca.w;
                    cp[4] = cb.x; cp[5] = cb.y; cp[6] = cb.z; cp[7] = cb.w;
                } else {
#pragma unroll
                    for (int k = 0; k < 8; k++) cp[k] = 0.f;
                }
#pragma unroll
                for (int k = 0; k < 8; k++) {
                    f[2 * k]     = cvt_tf32(cp[k] * lat[2 * k]);
                    f[2 * k + 1] = cvt_tf32(cp[k] * lat[2 * k + 1]);
                    f[16 + 2 * k]     = cvt_tf32(cp[k] * lat[16 + 2 * k]);
                    f[16 + 2 * k + 1] = cvt_tf32(cp[k] * lat[16 + 2 * k + 1]);
                }
            }
#pragma unroll
            for (int ch = 0; ch < 8; ch++) {
                float4 v = make_float4(f[ch * 4 + 0], f[ch * 4 + 1],
                                       f[ch * 4 + 2], f[ch * 4 + 3]);
                *(float4*)&smem[SD_A + tid * 32 + ((ch ^ (tid & 7)) << 2)] = v;
            }
        }
        __syncthreads();

        const int m0w = warp * 32;
        float sums[2][2] = {{0.f, 0.f}, {0.f, 0.f}};
        const float* SW = smem + SD_W;
        const float* SA = smem + SD_A;

        // A fragments hoisted: loaded once per node (addresses via col[])
        unsigned afr[2][4][4];
#pragma unroll
        for (int mt = 0; mt < 2; mt++) {
            const float* pa = SA + (m0w + mt * 16 + (lane >> 2)) * 32;
            const float* pb = pa + 8 * 32;
#pragma unroll
            for (int kt = 0; kt < 4; kt++) {
                afr[mt][kt][0] = __float_as_uint(pa[col[kt * 2]]);
                afr[mt][kt][1] = __float_as_uint(pb[col[kt * 2]]);
                afr[mt][kt][2] = __float_as_uint(pa[col[kt * 2 + 1]]);
                afr[mt][kt][3] = __float_as_uint(pb[col[kt * 2 + 1]]);
            }
        }

        for (int nh = 0; nh < 2; nh++) {
            unsigned bfr[4][4][2];
            float4 bwv[4];
#pragma unroll
            for (int nt = 0; nt < 4; nt++) {
                const float* pw = SW + (nh * 32 + nt * 8 + (lane >> 2)) * 32;
#pragma unroll
                for (int kt = 0; kt < 4; kt++) {
                    bfr[nt][kt][0] = __float_as_uint(pw[col[kt * 2]]);
                    bfr[nt][kt][1] = __float_as_uint(pw[col[kt * 2 + 1]]);
                }
                int j0 = nh * 32 + nt * 8 + (lane & 3) * 2;
                bwv[nt] = *(const float4*)&smem[SD_BW + (n * 64 + j0) * 2];
            }
#pragma unroll
            for (int mt = 0; mt < 2; mt++) {
#pragma unroll
                for (int nt = 0; nt < 4; nt++) {
                    float cfr[4] = {0.f, 0.f, 0.f, 0.f};
#pragma unroll
                    for (int kt = 0; kt < 4; kt++)
                        mma_tf32(cfr, afr[mt][kt], bfr[nt][kt]);
                    float4 bw2 = bwv[nt];
                    sums[mt][0] += fmaxf(cfr[0] + bw2.x, 0.f) * bw2.y +
                                   fmaxf(cfr[1] + bw2.z, 0.f) * bw2.w;
                    sums[mt][1] += fmaxf(cfr[2] + bw2.x, 0.f) * bw2.y +
                                   fmaxf(cfr[3] + bw2.z, 0.f) * bw2.w;
                }
            }
        }

        float be = smem[SD_BEFF + n];
#pragma unroll
        for (int mt = 0; mt < 2; mt++) {
#pragma unroll
            for (int h = 0; h < 2; h++) {
                float v = sums[mt][h];
                v += __shfl_xor_sync(0xffffffffu, v, 1);
                v += __shfl_xor_sync(0xffffffffu, v, 2);
                if ((lane & 3) == 0) {
                    int row = m0w + mt * 16 + h * 8 + (lane >> 2);
                    float val = fmaxf(v + be, 0.f);
                    if (row < 128) {
                        out[OFF_RECON + (size_t)(t0 + row) * 16 + n] = val;
                    } else {
                        size_t tt = (size_t)t0 + (row - 128) + 1;
                        if (tt < T_LEN)
                            out[OFF_PRED + tt * 16 + n] = val;
                    }
                }
            }
        }
        __syncthreads();
    }
}

// ---------------------------------------------------------------------------
extern "C" void kernel_launch(void* const* d_in, const int* in_sizes, int n_in,
                              void* d_out, int out_size) {
    const float* lm  = (const float*)d_in[0];
    const float* lv  = (const float*)d_in[1];
    const float* Tin = (const float*)d_in[2];
    const float* cw0 = (const float*)d_in[3];
    const float* cb0 = (const float*)d_in[4];
    const float* cw1 = (const float*)d_in[5];
    const float* cb1 = (const float*)d_in[6];
    const float* cw2 = (const float*)d_in[7];
    const float* cb2 = (const float*)d_in[8];
    const float* pw0 = (const float*)d_in[9];
    const float* pb0 = (const float*)d_in[10];
    const float* pw1 = (const float*)d_in[11];
    const float* pb1 = (const float*)d_in[12];
    const float* pw2 = (const float*)d_in[13];
    const float* pb2 = (const float*)d_in[14];
    const float* fmw1 = (const float*)d_in[15];
    const float* fmb1 = (const float*)d_in[16];
    const float* fmw2 = (const float*)d_in[17];
    const float* fmb2 = (const float*)d_in[18];
    const float* fvw1 = (const float*)d_in[19];
    const float* fvb1 = (const float*)d_in[20];
    const float* fvw2 = (const float*)d_in[21];
    const float* fvb2 = (const float*)d_in[22];
    const float* lw0 = (const float*)d_in[23];
    const float* lb0 = (const float*)d_in[24];
    const float* lw1 = (const float*)d_in[25];
    const float* lb1 = (const float*)d_in[26];
    const float* lw2 = (const float*)d_in[27];
    const float* lb2 = (const float*)d_in[28];
    float* out = (float*)d_out;

    cudaFuncSetAttribute(fused_kernel, cudaFuncAttributeMaxDynamicSharedMemorySize,
                         FUSED_SMEM_BYTES);

    prep_kernel<<<16, 256>>>(lw0, lw1, lw2, lb0, lb1, lb2, out);
    fused_kernel<<<DGRID, DB, FUSED_SMEM_BYTES>>>(
        lm, lv, Tin,
        cw0, cb0, cw1, cb1, cw2, cb2,
        pw0, pb0, pw1, pb1, pw2, pb2,
        fmw1, fmb1, fmw2, fmb2,
        fvw1, fvb1, fvw2, fvb2,
        lb0, out);
}

// round 15
// speedup vs baseline: 1.2827x; 1.1307x over previous
#include <cuda_runtime.h>
#include <cstdint>

#define T_LEN 131072
#define D_X 16
#define D_L 8

// d_out layout (flat concat of reference tuple, all float32)
#define OFF_RECON 0
#define OFF_PRED  (T_LEN * D_X)
#define OFF_LMP   (2 * T_LEN * D_X)
#define OFF_LVP   (OFF_LMP + 2 * T_LEN * D_L)
#define OFF_CT    (OFF_LVP + 2 * T_LEN * D_L)
#define OFF_CT1   (OFF_CT + T_LEN * D_X * D_L)

typedef unsigned long long u64;

// ---------------------------------------------------------------------------
// Packed fp32x2 helpers (verified head path)
// ---------------------------------------------------------------------------
__device__ __forceinline__ u64 pk2(float x, float y) {
    u64 r;
    asm("mov.b64 %0, {%1, %2};" : "=l"(r) : "f"(x), "f"(y));
    return r;
}
__device__ __forceinline__ void upk2(u64 a, float& x, float& y) {
    asm("mov.b64 {%0, %1}, %2;" : "=f"(x), "=f"(y) : "l"(a));
}
__device__ __forceinline__ u64 ffma2u(u64 a, u64 b, u64 c) {
    u64 d;
    asm("fma.rn.f32x2 %0, %1, %2, %3;" : "=l"(d) : "l"(a), "l"(b), "l"(c));
    return d;
}

// tf32 conversion + mma
__device__ __forceinline__ float cvt_tf32(float x) {
    float r;
    asm("cvt.rna.tf32.f32 %0, %1;" : "=f"(r) : "f"(x));
    return r;
}
__device__ __forceinline__ void mma_tf32(float* c, const unsigned* a,
                                         const unsigned* b) {
    asm volatile(
        "mma.sync.aligned.m16n8k8.row.col.f32.tf32.tf32.f32 "
        "{%0,%1,%2,%3}, {%4,%5,%6,%7}, {%8,%9}, {%0,%1,%2,%3};"
        : "+f"(c[0]), "+f"(c[1]), "+f"(c[2]), "+f"(c[3])
        : "r"(a[0]), "r"(a[1]), "r"(a[2]), "r"(a[3]), "r"(b[0]), "r"(b[1]));
}

// ---------------------------------------------------------------------------
// Device-global scratch (no allocation).
// ---------------------------------------------------------------------------
__device__ __align__(16) float g_w0t[D_X * 64 * 32];  // [n][j][f], tf32
__device__ __align__(16) float g_w12[D_X * 64];       // collapsed lw1@lw2
__device__ __align__(16) float g_beff[D_X];           // lb1@lw2 + lb2

// grid = 16 (one CTA per node), block = 256
__global__ void prep_kernel(const float* __restrict__ lw0,
                            const float* __restrict__ lw1,
                            const float* __restrict__ lw2,
                            const float* __restrict__ lb0,
                            const float* __restrict__ lb1,
                            const float* __restrict__ lb2,
                            float* __restrict__ out) {
    int n = blockIdx.x;
    int tid = threadIdx.x;
    int j = tid & 63;
    int q = tid >> 6;
#pragma unroll
    for (int ff = 0; ff < 8; ff++) {
        int f = q * 8 + ff;
        g_w0t[(n * 64 + j) * 32 + f] = cvt_tf32(lw0[(n * 32 + f) * 64 + j]);
    }
    if (q == 0) {
        float acc = 0.f;
#pragma unroll 8
        for (int o = 0; o < 64; o++)
            acc = fmaf(lw1[(n * 64 + j) * 64 + o], lw2[n * 64 + o], acc);
        g_w12[n * 64 + j] = acc;
        if (j == 0) {
            float b = lb2[n];
            for (int o = 0; o < 64; o++)
                b = fmaf(lb1[n * 64 + o], lw2[n * 64 + o], b);
            g_beff[n] = b;
        }
    }
    __syncthreads();
    if (tid == 0) {
        float s = g_beff[n];
        for (int o = 0; o < 64; o++) {
            float h = fmaxf(lb0[n * 64 + o], 0.f);
            s = fmaf(h, g_w12[n * 64 + o], s);
        }
        out[OFF_PRED + n] = fmaxf(s, 0.f);
    }
}

// ---------------------------------------------------------------------------
// Encoder (verified round-2 arithmetic): packed smem block per branch.
// ---------------------------------------------------------------------------
#define EW0 0
#define EB0 8
#define EW1 16
#define EB1 80
#define EW2 88
#define EB2 1112
#define ESZ 1240

__device__ __forceinline__ void enc01h(float s, const float* __restrict__ w,
                                       float* __restrict__ h1) {
    float h0[8];
#pragma unroll
    for (int i = 0; i < 8; i++) {
        float v = fmaf(s, w[EW0 + i], w[EB0 + i]);
        h0[i] = v > 0.f ? v : 0.01f * v;
    }
#pragma unroll
    for (int j = 0; j < 8; j++) {
        float a = 0.f;
#pragma unroll
        for (int i = 0; i < 8; i++) a = fmaf(h0[i], w[EW1 + i * 8 + j], a);
        a += w[EB1 + j];
        h1[j] = a > 0.f ? a : 0.01f * a;
    }
}

// full continuous branch (only used for Ct1 row 0; identical to verified)
__device__ __forceinline__ void enc_branch_cont(float s, const float* __restrict__ w,
                                                float* __restrict__ dst) {
    float h1[8];
    enc01h(s, w, h1);
#pragma unroll 4
    for (int m = 0; m < 128; m += 4) {
        float4 a = make_float4(0.f, 0.f, 0.f, 0.f);
#pragma unroll
        for (int j = 0; j < 8; j++) {
            float4 ww = *(const float4*)&w[EW2 + j * 128 + m];
            a.x = fmaf(h1[j], ww.x, a.x);
            a.y = fmaf(h1[j], ww.y, a.y);
            a.z = fmaf(h1[j], ww.z, a.z);
            a.w = fmaf(h1[j], ww.w, a.w);
        }
        a.x += w[EB2 + m + 0];
        a.y += w[EB2 + m + 1];
        a.z += w[EB2 + m + 2];
        a.w += w[EB2 + m + 3];
        *(float4*)&dst[m] = a;
    }
}

// half-range continuous branch into smem staging (identical per-m math)
__device__ __forceinline__ void enc_cont_half(const float* __restrict__ h1,
                                              const float* __restrict__ w,
                                              int c0, float* __restrict__ dst) {
#pragma unroll 4
    for (int m = c0; m < c0 + 64; m += 4) {
        float4 a = make_float4(0.f, 0.f, 0.f, 0.f);
#pragma unroll
        for (int j = 0; j < 8; j++) {
            float4 ww = *(const float4*)&w[EW2 + j * 128 + m];
            a.x = fmaf(h1[j], ww.x, a.x);
            a.y = fmaf(h1[j], ww.y, a.y);
            a.z = fmaf(h1[j], ww.z, a.z);
            a.w = fmaf(h1[j], ww.w, a.w);
        }
        a.x += w[EB2 + m + 0];
        a.y += w[EB2 + m + 1];
        a.z += w[EB2 + m + 2];
        a.w += w[EB2 + m + 3];
        *(float4*)&dst[m - c0] = a;
    }
}

// mask-only binarized branch (identical arithmetic; no stores)
__device__ __forceinline__ void enc_mask(float s, const float* __restrict__ w,
                                         u64& mlo, u64& mhi) {
    float h1[8];
    enc01h(s, w, h1);
    mlo = 0ull; mhi = 0ull;
#pragma unroll 4
    for (int m = 0; m < 128; m += 4) {
        float4 a = make_float4(0.f, 0.f, 0.f, 0.f);
#pragma unroll
        for (int j = 0; j < 8; j++) {
            float4 ww = *(const float4*)&w[EW2 + j * 128 + m];
            a.x = fmaf(h1[j], ww.x, a.x);
            a.y = fmaf(h1[j], ww.y, a.y);
            a.z = fmaf(h1[j], ww.z, a.z);
            a.w = fmaf(h1[j], ww.w, a.w);
        }
        a.x += w[EB2 + m + 0];
        a.y += w[EB2 + m + 1];
        a.z += w[EB2 + m + 2];
        a.w += w[EB2 + m + 3];
        unsigned bits = 0;
        if (!(a.x < 0.1f)) bits |= 1u;
        if (!(a.y < 0.1f)) bits |= 2u;
        if (!(a.z < 0.1f)) bits |= 4u;
        if (!(a.w < 0.1f)) bits |= 8u;
        if (m < 64) mlo |= (u64)bits << m;
        else        mhi |= (u64)bits << (m - 64);
    }
}

// ---------------------------------------------------------------------------
// Paired head (verified; x as packed register pairs); dst may be smem
// ---------------------------------------------------------------------------
__device__ __forceinline__ void head_fn2r(const u64* __restrict__ xa,
                                          const u64* __restrict__ xb,
                                          const float* __restrict__ w1t,
                                          const float* __restrict__ b1,
                                          const float* __restrict__ w2,
                                          const float* __restrict__ b2,
                                          float* __restrict__ dsta,
                                          float* __restrict__ dstb) {
    const ulonglong2* b2p = (const ulonglong2*)b2;
    ulonglong2 b2lo = b2p[0], b2hi = b2p[1];
    u64 oa0 = b2lo.x, oa1 = b2lo.y, oa2 = b2hi.x, oa3 = b2hi.y;
    u64 ob0 = oa0, ob1 = oa1, ob2 = oa2, ob3 = oa3;
    const ulonglong2* w1p = (const ulonglong2*)w1t;
    const ulonglong2* w2p = (const ulonglong2*)w2;
#pragma unroll 4
    for (int j = 0; j < 128; j++) {
        ulonglong2 wA = w1p[j * 2];
        ulonglong2 wB = w1p[j * 2 + 1];
        float bj = b1[j];
        u64 a0 = ffma2u(xa[0], wA.x, 0ull);
        u64 a1 = ffma2u(xa[2], wB.x, 0ull);
        a0 = ffma2u(xa[1], wA.y, a0);
        a1 = ffma2u(xa[3], wB.y, a1);
        u64 c0 = ffma2u(xb[0], wA.x, 0ull);
        u64 c1 = ffma2u(xb[2], wB.x, 0ull);
        c0 = ffma2u(xb[1], wA.y, c0);
        c1 = ffma2u(xb[3], wB.y, c1);
        float a0x, a0y, a1x, a1y, c0x, c0y, c1x, c1y;
        upk2(a0, a0x, a0y); upk2(a1, a1x, a1y);
        upk2(c0, c0x, c0y); upk2(c1, c1x, c1y);
        float ha = a0x + a0y + a1x + a1y + bj;
        float hb = c0x + c0y + c1x + c1y + bj;
        ha = fmaxf(ha, 0.f);
        hb = fmaxf(hb, 0.f);
        u64 hha = pk2(ha, ha);
        u64 hhb = pk2(hb, hb);
        ulonglong2 u = w2p[j * 2];
        ulonglong2 v = w2p[j * 2 + 1];
        oa0 = ffma2u(hha, u.x, oa0); oa1 = ffma2u(hha, u.y, oa1);
        oa2 = ffma2u(hha, v.x, oa2); oa3 = ffma2u(hha, v.y, oa3);
        ob0 = ffma2u(hhb, u.x, ob0); ob1 = ffma2u(hhb, u.y, ob1);
        ob2 = ffma2u(hhb, v.x, ob2); ob3 = ffma2u(hhb, v.y, ob3);
    }
    ulonglong2* da = (ulonglong2*)dsta;
    ulonglong2* db = (ulonglong2*)dstb;
    da[0] = make_ulonglong2(oa0, oa1);
    da[1] = make_ulonglong2(oa2, oa3);
    db[0] = make_ulonglong2(ob0, ob1);
    db[1] = make_ulonglong2(ob2, ob3);
}

// ---------------------------------------------------------------------------
// Fused kernel with coalesced output staging.
// ---------------------------------------------------------------------------
#define DB 256
#define DGRID (T_LEN / 128)   // 1024

// smem float offsets
#define SD_A    0                 // 8192 (A tile; also staging for Ct1/heads)
#define SD_W    8192              // 2048
#define SD_BW   10240             // 2048
#define SD_BEFF 12288             // 16
#define SD_RES  12304             // 256*20 = 5120 (results; mask xchg early)
#define E_C     17424             // 1240
#define E_P     (E_C + ESZ)
#define E_MW1T  (E_P + ESZ)
#define E_MB1   (E_MW1T + 1024)
#define E_MW2   (E_MB1 + 128)
#define E_MB2   (E_MW2 + 1024)
#define E_VW1T  (E_MB2 + 8)
#define E_VB1   (E_VW1T + 1024)
#define E_VW2   (E_VB1 + 128)
#define E_VB2   (E_VW2 + 1024)
#define SD_TOT  (E_VB2 + 8)
#define FUSED_SMEM_BYTES (SD_TOT * 4)   // ~97 KB -> 2 CTA/SM

__global__ __launch_bounds__(DB, 2)
void fused_kernel(const float* __restrict__ lm, const float* __restrict__ lv,
                  const float* __restrict__ Tin,
                  const float* cw0, const float* cb0, const float* cw1,
                  const float* cb1, const float* cw2, const float* cb2,
                  const float* pw0, const float* pb0, const float* pw1,
                  const float* pb1, const float* pw2, const float* pb2,
                  const float* fmw1, const float* fmb1,
                  const float* fmw2, const float* fmb2,
                  const float* fvw1, const float* fvb1,
                  const float* fvw2, const float* fvb2,
                  const float* __restrict__ lb0, float* __restrict__ out) {
    extern __shared__ __align__(16) float smem[];
    const int tid = threadIdx.x;
    const int warp = tid >> 5;
    const int lane = tid & 31;
    const int t0 = blockIdx.x * 128;
    const bool isRecon = tid < 128;
    const int rr = isRecon ? tid : tid - 128;
    const size_t tl = (size_t)t0 + rr;

    // ---- cooperative smem fill ----
    for (int i = tid; i < ESZ; i += DB) {
        float v, u;
        if (i < 8)         { v = cw0[i];        u = pw0[i];        }
        else if (i < 16)   { v = cb0[i - 8];    u = pb0[i - 8];    }
        else if (i < 80)   { v = cw1[i - 16];   u = pw1[i - 16];   }
        else if (i < 88)   { v = cb1[i - 80];   u = pb1[i - 80];   }
        else if (i < 1112) { v = cw2[i - 88];   u = pw2[i - 88];   }
        else               { v = cb2[i - 1112]; u = pb2[i - 1112]; }
        smem[E_C + i] = v;
        smem[E_P + i] = u;
    }
    for (int i = tid; i < 1024; i += DB) {
        int j = i >> 3, k = i & 7;
        smem[E_MW1T + i] = fmw1[k * 128 + j];
        smem[E_VW1T + i] = fvw1[k * 128 + j];
        smem[E_MW2 + i]  = fmw2[i];
        smem[E_VW2 + i]  = fvw2[i];
        smem[SD_BW + 2 * i]     = lb0[i];
        smem[SD_BW + 2 * i + 1] = g_w12[i];
    }
    if (tid < 128) { smem[E_MB1 + tid] = fmb1[tid]; smem[E_VB1 + tid] = fvb1[tid]; }
    if (tid < 8)   { smem[E_MB2 + tid] = fmb2[tid]; smem[E_VB2 + tid] = fvb2[tid]; }
    if (tid < 16)  smem[SD_BEFF + tid] = g_beff[tid];
    __syncthreads();

    // ---- latents register-resident (raw fp32 for enc/head phase) ----
    float lat[32];
    {
        const float4* lm4 = (const float4*)lm;
        const float4* lv4 = (const float4*)lv;
        float4 a0 = lm4[tl * 2], a1 = lm4[tl * 2 + 1];
        float4 b0 = lm4[((size_t)T_LEN + tl) * 2], b1 = lm4[((size_t)T_LEN + tl) * 2 + 1];
        float4 c0 = lv4[tl * 2], c1 = lv4[tl * 2 + 1];
        float4 d0 = lv4[((size_t)T_LEN + tl) * 2], d1 = lv4[((size_t)T_LEN + tl) * 2 + 1];
        float M0[8] = {a0.x, a0.y, a0.z, a0.w, a1.x, a1.y, a1.z, a1.w};
        float M1[8] = {b0.x, b0.y, b0.z, b0.w, b1.x, b1.y, b1.z, b1.w};
        float V0[8] = {c0.x, c0.y, c0.z, c0.w, c1.x, c1.y, c1.z, c1.w};
        float V1[8] = {d0.x, d0.y, d0.z, d0.w, d1.x, d1.y, d1.z, d1.w};
#pragma unroll
        for (int k = 0; k < 8; k++) {
            lat[2 * k]     = M0[k];
            lat[2 * k + 1] = M1[k];
            lat[16 + 2 * k]     = V0[k];
            lat[16 + 2 * k + 1] = V1[k];
        }
    }

    // ---- enc phase ----
    u64 mlo = 0ull, mhi = 0ull;
    float h1q[8];
    if (isRecon) {
        enc_mask(Tin[tl], smem + E_C, mlo, mhi);
        ((ulonglong2*)(smem + SD_RES))[rr] = make_ulonglong2(mlo, mhi);
        if (t0 == 0 && tid == 0)
            enc_branch_cont(Tin[0], smem + E_P, out + OFF_CT1);
    } else {
        size_t tt = tl + 1;
        float s2 = (tt < T_LEN) ? Tin[tt] : 0.f;
        enc01h(s2, smem + E_P, h1q);
    }
    __syncthreads();

    // ---- Ct flush (coalesced, from masks) ----
    {
        const ulonglong2* mk = (const ulonglong2*)(smem + SD_RES);
        float* ctbase = out + OFF_CT + (size_t)t0 * 128;
#pragma unroll
        for (int q = 0; q < 16; q++) {
            int g = q * 1024 + tid * 4;
            int r = g >> 7;
            int m = g & 127;
            ulonglong2 mv = mk[r];
            u64 half = (m < 64) ? mv.x : mv.y;
            unsigned nib = (unsigned)(half >> (m & 63)) & 0xFu;
            float4 v = make_float4((nib & 1u) ? 1.f : 0.f,
                                   (nib & 2u) ? 1.f : 0.f,
                                   (nib & 4u) ? 1.f : 0.f,
                                   (nib & 8u) ? 1.f : 0.f);
            *(float4*)&ctbase[g] = v;
        }
    }

    // ---- Ct1: two staged passes (cols 0-63, 64-127), coalesced flush ----
    {
        float* stg = smem + SD_A;   // row stride 68
#pragma unroll
        for (int pass = 0; pass < 2; pass++) {
            if (!isRecon)
                enc_cont_half(h1q, smem + E_P, pass * 64, stg + rr * 68);
            __syncthreads();
#pragma unroll
            for (int q = 0; q < 8; q++) {
                int g = q * 1024 + tid * 4;
                int r = g >> 6, c = g & 63;
                size_t tt = (size_t)t0 + 1 + r;
                if (tt < T_LEN) {
                    float4 v = *(const float4*)&stg[r * 68 + c];
                    *(float4*)&out[OFF_CT1 + tt * 128 + pass * 64 + c] = v;
                }
            }
            __syncthreads();
        }
    }

    // ---- head phase: staged to smem tiles (stride 12), coalesced flush ----
    {
        u64 xa[4], xb[4];
        int base = isRecon ? 0 : 16;
#pragma unroll
        for (int i = 0; i < 4; i++) {
            xa[i] = pk2(lat[base + 4 * i], lat[base + 4 * i + 2]);
            xb[i] = pk2(lat[base + 4 * i + 1], lat[base + 4 * i + 3]);
        }
        const float* w1t = isRecon ? smem + E_MW1T : smem + E_VW1T;
        const float* b1h = isRecon ? smem + E_MB1  : smem + E_VB1;
        const float* w2h = isRecon ? smem + E_MW2  : smem + E_VW2;
        const float* b2h = isRecon ? smem + E_MB2  : smem + E_VB2;
        float* da = smem + SD_A + (isRecon ? 0 : 3072) + rr * 12;
        float* db = da + 1536;
        head_fn2r(xa, xb, w1t, b1h, w2h, b2h, da, db);
    }
    __syncthreads();
    {
        int g = tid * 16;
        int tile = g >> 10;
        int rem = g & 1023;
        size_t gbase = (size_t)((tile < 2) ? OFF_LMP : OFF_LVP) +
                       ((tile & 1) ? ((size_t)T_LEN + t0) : (size_t)t0) * 8;
        const float* src = smem + SD_A + tile * 1536;
        float* dstg = out + gbase;
#pragma unroll
        for (int q = 0; q < 4; q++) {
            int rem2 = rem + q * 4;
            int r = rem2 >> 3, c = rem2 & 7;
            float4 v = *(const float4*)&src[r * 12 + c];
            *(float4*)&dstg[rem2] = v;
        }
    }
    __syncthreads();

    // recon lat -> tf32
    if (isRecon) {
#pragma unroll
        for (int i = 0; i < 32; i++) lat[i] = cvt_tf32(lat[i]);
    }

    // per-thread swizzle column offsets (constant across nodes)
    int col[8];
#pragma unroll
    for (int k2 = 0; k2 < 8; k2++)
        col[k2] = (((k2 ^ (lane >> 2)) << 2) + (lane & 3));

    // ---- decode node loop (R14 structure; epilogue -> smem res) ----
    for (int n = 0; n < D_X; n++) {
        for (int i = tid; i < 512; i += DB) {
            int j = i >> 3, ch = i & 7;
            float4 w = ((const float4*)(g_w0t + n * 2048))[i];
            *(float4*)&smem[SD_W + j * 32 + ((ch ^ (j & 7)) << 2)] = w;
        }
        {
            float f[32];
            if (isRecon) {
                unsigned byte = (unsigned)((n < 8 ? (mlo >> (8 * n))
                                                  : (mhi >> (8 * (n - 8)))) & 0xffu);
#pragma unroll
                for (int k = 0; k < 8; k++) {
                    bool on = (byte >> k) & 1u;
                    f[2 * k]     = on ? lat[2 * k] : 0.f;
                    f[2 * k + 1] = on ? lat[2 * k + 1] : 0.f;
                    f[16 + 2 * k]     = on ? lat[16 + 2 * k] : 0.f;
                    f[16 + 2 * k + 1] = on ? lat[16 + 2 * k + 1] : 0.f;
                }
            } else {
                size_t tt = tl + 1;
                float cp[8];
                if (tt < T_LEN) {
                    const float4* c4 = (const float4*)(out + OFF_CT1 + tt * 128 + n * 8);
                    float4 ca = c4[0], cb = c4[1];
                    cp[0] = ca.x; cp[1] = ca.y; cp[2] = ca.z; cp[3] = ca.w;
                    cp[4] = cb.x; cp[5] = cb.y; cp[6] = cb.z; cp[7] = cb.w;
                } else {
#pragma unroll
                    for (int k = 0; k < 8; k++) cp[k] = 0.f;
                }
#pragma unroll
                for (int k = 0; k < 8; k++) {
                    f[2 * k]     = cvt_tf32(cp[k] * lat[2 * k]);
                    f[2 * k + 1] = cvt_tf32(cp[k] * lat[2 * k + 1]);
                    f[16 + 2 * k]     = cvt_tf32(cp[k] * lat[16 + 2 * k]);
                    f[16 + 2 * k + 1] = cvt_tf32(cp[k] * lat[16 + 2 * k + 1]);
                }
            }
#pragma unroll
            for (int ch = 0; ch < 8; ch++) {
                float4 v = make_float4(f[ch * 4 + 0], f[ch * 4 + 1],
                                       f[ch * 4 + 2], f[ch * 4 + 3]);
                *(float4*)&smem[SD_A + tid * 32 + ((ch ^ (tid & 7)) << 2)] = v;
            }
        }
        __syncthreads();

        const int m0w = warp * 32;
        float sums[2][2] = {{0.f, 0.f}, {0.f, 0.f}};
        const float* SW = smem + SD_W;
        const float* SA = smem + SD_A;

        unsigned afr[2][4][4];
#pragma unroll
        for (int mt = 0; mt < 2; mt++) {
            const float* pa = SA + (m0w + mt * 16 + (lane >> 2)) * 32;
            const float* pb = pa + 8 * 32;
#pragma unroll
            for (int kt = 0; kt < 4; kt++) {
                afr[mt][kt][0] = __float_as_uint(pa[col[kt * 2]]);
                afr[mt][kt][1] = __float_as_uint(pb[col[kt * 2]]);
                afr[mt][kt][2] = __float_as_uint(pa[col[kt * 2 + 1]]);
                afr[mt][kt][3] = __float_as_uint(pb[col[kt * 2 + 1]]);
            }
        }

        for (int nh = 0; nh < 2; nh++) {
            unsigned bfr[4][4][2];
            float4 bwv[4];
#pragma unroll
            for (int nt = 0; nt < 4; nt++) {
                const float* pw = SW + (nh * 32 + nt * 8 + (lane >> 2)) * 32;
#pragma unroll
                for (int kt = 0; kt < 4; kt++) {
                    bfr[nt][kt][0] = __float_as_uint(pw[col[kt * 2]]);
                    bfr[nt][kt][1] = __float_as_uint(pw[col[kt * 2 + 1]]);
                }
                int j0 = nh * 32 + nt * 8 + (lane & 3) * 2;
                bwv[nt] = *(const float4*)&smem[SD_BW + (n * 64 + j0) * 2];
            }
#pragma unroll
            for (int mt = 0; mt < 2; mt++) {
#pragma unroll
                for (int nt = 0; nt < 4; nt++) {
                    float cfr[4] = {0.f, 0.f, 0.f, 0.f};
#pragma unroll
                    for (int kt = 0; kt < 4; kt++)
                        mma_tf32(cfr, afr[mt][kt], bfr[nt][kt]);
                    float4 bw2 = bwv[nt];
                    sums[mt][0] += fmaxf(cfr[0] + bw2.x, 0.f) * bw2.y +
                                   fmaxf(cfr[1] + bw2.z, 0.f) * bw2.w;
                    sums[mt][1] += fmaxf(cfr[2] + bw2.x, 0.f) * bw2.y +
                                   fmaxf(cfr[3] + bw2.z, 0.f) * bw2.w;
                }
            }
        }

        float be = smem[SD_BEFF + n];
#pragma unroll
        for (int mt = 0; mt < 2; mt++) {
#pragma unroll
            for (int h = 0; h < 2; h++) {
                float v = sums[mt][h];
                v += __shfl_xor_sync(0xffffffffu, v, 1);
                v += __shfl_xor_sync(0xffffffffu, v, 2);
                if ((lane & 3) == 0) {
                    int row = m0w + mt * 16 + h * 8 + (lane >> 2);
                    smem[SD_RES + row * 20 + n] = fmaxf(v + be, 0.f);
                }
            }
        }
        __syncthreads();
    }

    // ---- final coalesced flush of recon/pred ----
#pragma unroll
    for (int q = 0; q < 2; q++) {
        int g = q * 1024 + tid * 4;
        int r = g >> 4, n = g & 15;
        float4 v = *(const float4*)&smem[SD_RES + r * 20 + n];
        *(float4*)&out[OFF_RECON + (size_t)(t0 + r) * 16 + n] = v;
    }
#pragma unroll
    for (int q = 0; q < 2; q++) {
        int g = q * 1024 + tid * 4;
        int r = g >> 4, n = g & 15;
        size_t tt = (size_t)t0 + 1 + r;
        if (tt < T_LEN) {
            float4 v = *(const float4*)&smem[SD_RES + (128 + r) * 20 + n];
            *(float4*)&out[OFF_PRED + tt * 16 + n] = v;
        }
    }
}

// ---------------------------------------------------------------------------
extern "C" void kernel_launch(void* const* d_in, const int* in_sizes, int n_in,
                              void* d_out, int out_size) {
    const float* lm  = (const float*)d_in[0];
    const float* lv  = (const float*)d_in[1];
    const float* Tin = (const float*)d_in[2];
    const float* cw0 = (const float*)d_in[3];
    const float* cb0 = (const float*)d_in[4];
    const float* cw1 = (const float*)d_in[5];
    const float* cb1 = (const float*)d_in[6];
    const float* cw2 = (const float*)d_in[7];
    const float* cb2 = (const float*)d_in[8];
    const float* pw0 = (const float*)d_in[9];
    const float* pb0 = (const float*)d_in[10];
    const float* pw1 = (const float*)d_in[11];
    const float* pb1 = (const float*)d_in[12];
    const float* pw2 = (const float*)d_in[13];
    const float* pb2 = (const float*)d_in[14];
    const float* fmw1 = (const float*)d_in[15];
    const float* fmb1 = (const float*)d_in[16];
    const float* fmw2 = (const float*)d_in[17];
    const float* fmb2 = (const float*)d_in[18];
    const float* fvw1 = (const float*)d_in[19];
    const float* fvb1 = (const float*)d_in[20];
    const float* fvw2 = (const float*)d_in[21];
    const float* fvb2 = (const float*)d_in[22];
    const float* lw0 = (const float*)d_in[23];
    const float* lb0 = (const float*)d_in[24];
    const float* lw1 = (const float*)d_in[25];
    const float* lb1 = (const float*)d_in[26];
    const float* lw2 = (const float*)d_in[27];
    const float* lb2 = (const float*)d_in[28];
    float* out = (float*)d_out;

    cudaFuncSetAttribute(fused_kernel, cudaFuncAttributeMaxDynamicSharedMemorySize,
                         FUSED_SMEM_BYTES);

    prep_kernel<<<16, 256>>>(lw0, lw1, lw2, lb0, lb1, lb2, out);
    fused_kernel<<<DGRID, DB, FUSED_SMEM_BYTES>>>(
        lm, lv, Tin,
        cw0, cb0, cw1, cb1, cw2, cb2,
        pw0, pb0, pw1, pb1, pw2, pb2,
        fmw1, fmb1, fmw2, fmb2,
        fvw1, fvb1, fvw2, fvb2,
        lb0, out);
}